// round 1
// baseline (speedup 1.0000x reference)
#include <cuda_runtime.h>
#include <math.h>

#define NB   32      // batch
#define NT   4096    // sequence
#define NCAT 128
#define NNE  512
#define NHS  64
#define NCHUNK 32            // t-chunks for pass-2 partials
#define TCHUNK (NT / NCHUNK) // 128

// ---- scratch (device globals; no allocations allowed) ----
__device__ float g_qk[NB * NNE];            // folded q·Wk^T with scale
__device__ float g_scores[NB * NT];         // scores, then softmax weights (in-place)
__device__ float g_xap[NB * NCHUNK * NNE];  // partial weighted sums of x
__device__ float g_y[NB * NNE];             // final per-batch row

// ============================================================
// Kernel A: q[b] = cat_emb[b] @ Wq ; qk[b,n] = scale * sum_h Wk[n,h] q[h]
// grid: NB blocks, 512 threads
// ============================================================
__global__ void kA(const float* __restrict__ cat_emb,
                   const float* __restrict__ Wq,
                   const float* __restrict__ Wk) {
    const int b = blockIdx.x;
    const int tid = threadIdx.x;
    __shared__ float qs[NHS];

    if (tid < NHS) {
        float acc = 0.f;
        const float* ce = cat_emb + b * NCAT;
        #pragma unroll 8
        for (int c = 0; c < NCAT; ++c)
            acc += ce[c] * Wq[c * NHS + tid];
        qs[tid] = acc;
    }
    __syncthreads();

    float acc = 0.f;
    const float* wkr = Wk + tid * NHS;
    #pragma unroll
    for (int h = 0; h < NHS; ++h)
        acc += wkr[h] * qs[h];
    g_qk[b * NNE + tid] = acc * 0.125f;  // 1/sqrt(64)
}

// ============================================================
// Kernel B: scores[b,t] = x[b,t,:] . qk[b,:]
// grid: (NT/ROWS_B, NB), 256 threads (8 warps), warp per row
// ============================================================
#define ROWS_B 128
__global__ void kB(const float* __restrict__ x) {
    const int b = blockIdx.y;
    const int tid = threadIdx.x;
    const int warp = tid >> 5, lane = tid & 31;

    __shared__ float4 qk4[NNE / 4];  // 128 float4
    if (tid < NNE / 4)
        qk4[tid] = reinterpret_cast<const float4*>(g_qk + b * NNE)[tid];
    __syncthreads();

    const int t0 = blockIdx.x * ROWS_B;
    for (int r = warp; r < ROWS_B; r += 8) {
        const int t = t0 + r;
        const float4* xr = reinterpret_cast<const float4*>(
            x + ((size_t)b * NT + t) * NNE);
        float acc = 0.f;
        #pragma unroll
        for (int i = 0; i < 4; ++i) {
            const int idx = lane + i * 32;
            float4 xv = xr[idx];
            float4 qv = qk4[idx];
            acc += xv.x * qv.x + xv.y * qv.y + xv.z * qv.z + xv.w * qv.w;
        }
        #pragma unroll
        for (int o = 16; o > 0; o >>= 1)
            acc += __shfl_xor_sync(0xffffffffu, acc, o);
        if (lane == 0)
            g_scores[b * NT + t] = acc;
    }
}

// ============================================================
// Kernel C: softmax over T, in place. grid: NB blocks, 1024 threads
// ============================================================
__global__ void kC() {
    const int b = blockIdx.x;
    const int tid = threadIdx.x;
    const int warp = tid >> 5, lane = tid & 31;
    float* s = g_scores + b * NT;

    __shared__ float red[32];
    __shared__ float bcast;

    float v[4];
    float m = -INFINITY;
    #pragma unroll
    for (int i = 0; i < 4; ++i) {
        v[i] = s[tid + i * 1024];
        m = fmaxf(m, v[i]);
    }
    #pragma unroll
    for (int o = 16; o > 0; o >>= 1)
        m = fmaxf(m, __shfl_xor_sync(0xffffffffu, m, o));
    if (lane == 0) red[warp] = m;
    __syncthreads();
    if (tid < 32) {
        float mm = red[tid];
        #pragma unroll
        for (int o = 16; o > 0; o >>= 1)
            mm = fmaxf(mm, __shfl_xor_sync(0xffffffffu, mm, o));
        if (tid == 0) bcast = mm;
    }
    __syncthreads();
    const float M = bcast;
    __syncthreads();  // protect red[] reuse

    float sum = 0.f;
    #pragma unroll
    for (int i = 0; i < 4; ++i) {
        v[i] = expf(v[i] - M);
        sum += v[i];
    }
    #pragma unroll
    for (int o = 16; o > 0; o >>= 1)
        sum += __shfl_xor_sync(0xffffffffu, sum, o);
    if (lane == 0) red[warp] = sum;
    __syncthreads();
    if (tid < 32) {
        float ss = red[tid];
        #pragma unroll
        for (int o = 16; o > 0; o >>= 1)
            ss += __shfl_xor_sync(0xffffffffu, ss, o);
        if (tid == 0) bcast = ss;
    }
    __syncthreads();
    const float inv = 1.f / bcast;

    #pragma unroll
    for (int i = 0; i < 4; ++i)
        s[tid + i * 1024] = v[i] * inv;
}

// ============================================================
// Kernel D: partial weighted sums: xap[b,chunk,n] = sum_{t in chunk} w[t] x[b,t,n]
// grid: (NCHUNK, NB), 256 threads; each thread owns 2 n-slots in registers
// ============================================================
__global__ void kD(const float* __restrict__ x) {
    const int b = blockIdx.y;
    const int chunk = blockIdx.x;
    const int tid = threadIdx.x;

    const float* __restrict__ w = g_scores + b * NT + chunk * TCHUNK;
    const float* __restrict__ xp = x + ((size_t)b * NT + (size_t)chunk * TCHUNK) * NNE;

    float a0 = 0.f, a1 = 0.f;
    #pragma unroll 4
    for (int t = 0; t < TCHUNK; ++t) {
        const float wt = __ldg(w + t);
        const float* row = xp + (size_t)t * NNE;
        a0 = fmaf(wt, row[tid],       a0);
        a1 = fmaf(wt, row[tid + 256], a1);
    }
    float* xap = g_xap + ((size_t)b * NCHUNK + chunk) * NNE;
    xap[tid]       = a0;
    xap[tid + 256] = a1;
}

// ============================================================
// Kernel E: xa = reduce(xap); out = xa@Wv; y = out@Wp; LayerNorm -> g_y
// grid: NB blocks, 512 threads (16 warps)
// ============================================================
__global__ void kE(const float* __restrict__ Wv,
                   const float* __restrict__ Wp,
                   const float* __restrict__ gamma,
                   const float* __restrict__ beta) {
    const int b = blockIdx.x;
    const int tid = threadIdx.x;
    const int warp = tid >> 5, lane = tid & 31;

    __shared__ float xa[NNE];
    __shared__ float outh[NHS];
    __shared__ float red[16];
    __shared__ float bcast;

    // deterministic partial reduction (fixed order)
    float acc = 0.f;
    #pragma unroll
    for (int c = 0; c < NCHUNK; ++c)
        acc += g_xap[((size_t)b * NCHUNK + c) * NNE + tid];
    xa[tid] = acc;
    __syncthreads();

    if (tid < NHS) {
        float o = 0.f;
        #pragma unroll 8
        for (int n = 0; n < NNE; ++n)
            o += xa[n] * Wv[n * NHS + tid];
        outh[tid] = o;
    }
    __syncthreads();

    float y = 0.f;
    #pragma unroll
    for (int h = 0; h < NHS; ++h)
        y += outh[h] * Wp[h * NNE + tid];

    // mean
    float s = y;
    #pragma unroll
    for (int o = 16; o > 0; o >>= 1)
        s += __shfl_xor_sync(0xffffffffu, s, o);
    if (lane == 0) red[warp] = s;
    __syncthreads();
    if (tid < 32) {
        float ss = (tid < 16) ? red[tid] : 0.f;
        #pragma unroll
        for (int o = 16; o > 0; o >>= 1)
            ss += __shfl_xor_sync(0xffffffffu, ss, o);
        if (tid == 0) bcast = ss;
    }
    __syncthreads();
    const float mu = bcast * (1.f / NNE);
    __syncthreads();

    // variance
    const float d = y - mu;
    float vs = d * d;
    #pragma unroll
    for (int o = 16; o > 0; o >>= 1)
        vs += __shfl_xor_sync(0xffffffffu, vs, o);
    if (lane == 0) red[warp] = vs;
    __syncthreads();
    if (tid < 32) {
        float ss = (tid < 16) ? red[tid] : 0.f;
        #pragma unroll
        for (int o = 16; o > 0; o >>= 1)
            ss += __shfl_xor_sync(0xffffffffu, ss, o);
        if (tid == 0) bcast = ss;
    }
    __syncthreads();
    const float var = bcast * (1.f / NNE);
    const float rstd = rsqrtf(var + 1e-5f);

    g_y[b * NNE + tid] = d * rstd * gamma[tid] + beta[tid];
}

// ============================================================
// Kernel F: broadcast g_y[b,:] to out[b, t, :] for all t
// grid: (NT/ROWS_F, NB), 128 threads; float4 stores
// ============================================================
#define ROWS_F 32
__global__ void kF(float* __restrict__ out) {
    const int b = blockIdx.y;
    const int tid = threadIdx.x;  // 128 = NNE/4

    const float4 val = reinterpret_cast<const float4*>(g_y + b * NNE)[tid];

    const int t0 = blockIdx.x * ROWS_F;
    float4* o = reinterpret_cast<float4*>(out + ((size_t)b * NT + t0) * NNE);
    #pragma unroll 4
    for (int r = 0; r < ROWS_F; ++r)
        o[(size_t)r * (NNE / 4) + tid] = val;
}

// ============================================================
extern "C" void kernel_launch(void* const* d_in, const int* in_sizes, int n_in,
                              void* d_out, int out_size) {
    const float* x       = (const float*)d_in[0];
    const float* cat_emb = (const float*)d_in[1];
    const float* Wq      = (const float*)d_in[2];
    const float* Wk      = (const float*)d_in[3];
    const float* Wv      = (const float*)d_in[4];
    const float* Wp      = (const float*)d_in[5];
    const float* gamma   = (const float*)d_in[6];
    const float* beta    = (const float*)d_in[7];
    float* out = (float*)d_out;

    kA<<<NB, NNE>>>(cat_emb, Wq, Wk);
    kB<<<dim3(NT / ROWS_B, NB), 256>>>(x);
    kC<<<NB, 1024>>>();
    kD<<<dim3(NCHUNK, NB), 256>>>(x);
    kE<<<NB, NNE>>>(Wv, Wp, gamma, beta);
    kF<<<dim3(NT / ROWS_F, NB), 128>>>(out);
}

// round 2
// speedup vs baseline: 1.2515x; 1.2515x over previous
#include <cuda_runtime.h>
#include <math.h>

#define NB   32      // batch
#define NT   4096    // sequence
#define NCAT 128
#define NNE  512
#define NHS  64

#define NBLK 32              // blocks per batch in fused kernel
#define TPB  (NT / NBLK)     // 128 t per block
#define WARPS 8
#define TPW  (TPB / WARPS)   // 16 rows per warp

// ---- scratch (device globals; no allocations allowed) ----
__device__ float g_qk[NB * NNE];              // folded scale * Wk @ (cat_emb @ Wq)
__device__ float g_pm[NB * NBLK];             // partial running max
__device__ float g_ps[NB * NBLK];             // partial exp-sum
__device__ float g_pacc[NB * NBLK * NNE];     // partial weighted sums (unnormalized)
__device__ float g_y[NB * NNE];               // final per-batch row

// ============================================================
// Kernel A: q[b] = cat_emb[b] @ Wq ; qk[b,n] = scale * sum_h Wk[n,h] q[h]
// grid: NB blocks, 512 threads
// ============================================================
__global__ void kA(const float* __restrict__ cat_emb,
                   const float* __restrict__ Wq,
                   const float* __restrict__ Wk) {
    const int b = blockIdx.x;
    const int tid = threadIdx.x;
    __shared__ float qs[NHS];

    if (tid < NHS) {
        float acc = 0.f;
        const float* ce = cat_emb + b * NCAT;
        #pragma unroll 8
        for (int c = 0; c < NCAT; ++c)
            acc += ce[c] * Wq[c * NHS + tid];
        qs[tid] = acc;
    }
    __syncthreads();

    float acc = 0.f;
    const float* wkr = Wk + tid * NHS;
    #pragma unroll
    for (int h = 0; h < NHS; ++h)
        acc += wkr[h] * qs[h];
    g_qk[b * NNE + tid] = acc * 0.125f;  // 1/sqrt(64)
}

// ============================================================
// Fused kernel: scores + online softmax + weighted x-sum, ONE pass over x.
// grid: (NBLK, NB), 256 threads (8 warps). Warp owns 16 contiguous rows.
// Per-warp state in registers: running max m, exp-sum S, acc[16 floats/lane].
// ============================================================
__global__ void kFuse(const float* __restrict__ x) {
    const int b = blockIdx.y;
    const int blk = blockIdx.x;
    const int tid = threadIdx.x;
    const int warp = tid >> 5, lane = tid & 31;

    // qk in registers, same lane layout as x rows: float4 idx lane+32i
    const float4* qkp = reinterpret_cast<const float4*>(g_qk + b * NNE);
    float4 qv[4];
    #pragma unroll
    for (int i = 0; i < 4; ++i) qv[i] = qkp[lane + 32 * i];

    const int t0 = blk * TPB + warp * TPW;
    const float4* xbase = reinterpret_cast<const float4*>(
        x + ((size_t)b * NT + t0) * NNE);

    float m = -INFINITY, S = 0.f;
    float4 acc[4];
    #pragma unroll
    for (int i = 0; i < 4; ++i) acc[i] = make_float4(0.f, 0.f, 0.f, 0.f);

    #pragma unroll 2
    for (int t = 0; t < TPW; ++t) {
        float4 xv[4];
        const float4* xr = xbase + (size_t)t * (NNE / 4);
        #pragma unroll
        for (int i = 0; i < 4; ++i) xv[i] = xr[lane + 32 * i];

        // score = x_row . qk (qk already carries the 1/sqrt(HS) scale)
        float d = 0.f;
        #pragma unroll
        for (int i = 0; i < 4; ++i)
            d += xv[i].x * qv[i].x + xv[i].y * qv[i].y +
                 xv[i].z * qv[i].z + xv[i].w * qv[i].w;
        #pragma unroll
        for (int o = 16; o > 0; o >>= 1)
            d += __shfl_xor_sync(0xffffffffu, d, o);

        // online softmax update (expf(-inf)=0 handles first iter)
        const float newm = fmaxf(m, d);
        const float sc = __expf(m - newm);
        const float w  = __expf(d - newm);
        S = S * sc + w;
        #pragma unroll
        for (int i = 0; i < 4; ++i) {
            acc[i].x = acc[i].x * sc + w * xv[i].x;
            acc[i].y = acc[i].y * sc + w * xv[i].y;
            acc[i].z = acc[i].z * sc + w * xv[i].z;
            acc[i].w = acc[i].w * sc + w * xv[i].w;
        }
        m = newm;
    }

    // ---- block combine across 8 warps ----
    __shared__ float sm[WARPS], ss[WARPS];
    __shared__ float sacc[WARPS][NNE];  // 16 KB
    if (lane == 0) { sm[warp] = m; ss[warp] = S; }
    float4* sa4 = reinterpret_cast<float4*>(sacc[warp]);
    #pragma unroll
    for (int i = 0; i < 4; ++i) sa4[lane + 32 * i] = acc[i];
    __syncthreads();

    float mb = sm[0];
    #pragma unroll
    for (int w2 = 1; w2 < WARPS; ++w2) mb = fmaxf(mb, sm[w2]);

    float a0 = 0.f, a1 = 0.f, Sb = 0.f;
    #pragma unroll
    for (int w2 = 0; w2 < WARPS; ++w2) {
        const float f = __expf(sm[w2] - mb);
        Sb += ss[w2] * f;
        a0 += sacc[w2][tid] * f;
        a1 += sacc[w2][tid + 256] * f;
    }
    const int p = b * NBLK + blk;
    g_pacc[(size_t)p * NNE + tid]       = a0;
    g_pacc[(size_t)p * NNE + tid + 256] = a1;
    if (tid == 0) { g_pm[p] = mb; g_ps[p] = Sb; }
}

// ============================================================
// Kernel E: combine partials -> xa; out = xa@Wv; y = out@Wp; LayerNorm -> g_y
// grid: NB blocks, 512 threads (16 warps)
// ============================================================
__global__ void kE(const float* __restrict__ Wv,
                   const float* __restrict__ Wp,
                   const float* __restrict__ gamma,
                   const float* __restrict__ beta) {
    const int b = blockIdx.x;
    const int tid = threadIdx.x;
    const int warp = tid >> 5, lane = tid & 31;

    __shared__ float xa[NNE];
    __shared__ float outh[NHS];
    __shared__ float red[16];
    __shared__ float bcast;

    // global max / sum over NBLK partials (redundant per thread; cheap)
    float mb = -INFINITY;
    #pragma unroll
    for (int c = 0; c < NBLK; ++c)
        mb = fmaxf(mb, g_pm[b * NBLK + c]);
    float Sb = 0.f;
    #pragma unroll
    for (int c = 0; c < NBLK; ++c)
        Sb += g_ps[b * NBLK + c] * __expf(g_pm[b * NBLK + c] - mb);

    float acc = 0.f;
    #pragma unroll
    for (int c = 0; c < NBLK; ++c)
        acc += g_pacc[((size_t)b * NBLK + c) * NNE + tid] *
               __expf(g_pm[b * NBLK + c] - mb);
    xa[tid] = acc / Sb;
    __syncthreads();

    if (tid < NHS) {
        float o = 0.f;
        #pragma unroll 8
        for (int n = 0; n < NNE; ++n)
            o += xa[n] * Wv[n * NHS + tid];
        outh[tid] = o;
    }
    __syncthreads();

    float y = 0.f;
    #pragma unroll
    for (int h = 0; h < NHS; ++h)
        y += outh[h] * Wp[h * NNE + tid];

    // mean
    float s = y;
    #pragma unroll
    for (int o = 16; o > 0; o >>= 1)
        s += __shfl_xor_sync(0xffffffffu, s, o);
    if (lane == 0) red[warp] = s;
    __syncthreads();
    if (tid < 32) {
        float ss2 = (tid < 16) ? red[tid] : 0.f;
        #pragma unroll
        for (int o = 16; o > 0; o >>= 1)
            ss2 += __shfl_xor_sync(0xffffffffu, ss2, o);
        if (tid == 0) bcast = ss2;
    }
    __syncthreads();
    const float mu = bcast * (1.f / NNE);
    __syncthreads();

    // variance
    const float d = y - mu;
    float vs = d * d;
    #pragma unroll
    for (int o = 16; o > 0; o >>= 1)
        vs += __shfl_xor_sync(0xffffffffu, vs, o);
    if (lane == 0) red[warp] = vs;
    __syncthreads();
    if (tid < 32) {
        float ss2 = (tid < 16) ? red[tid] : 0.f;
        #pragma unroll
        for (int o = 16; o > 0; o >>= 1)
            ss2 += __shfl_xor_sync(0xffffffffu, ss2, o);
        if (tid == 0) bcast = ss2;
    }
    __syncthreads();
    const float var = bcast * (1.f / NNE);
    const float rstd = rsqrtf(var + 1e-5f);

    g_y[b * NNE + tid] = d * rstd * gamma[tid] + beta[tid];
}

// ============================================================
// Kernel F: broadcast g_y[b,:] to out[b, t, :] for all t
// grid: (NT/ROWS_F, NB), 128 threads; float4 stores
// ============================================================
#define ROWS_F 32
__global__ void kF(float* __restrict__ out) {
    const int b = blockIdx.y;
    const int tid = threadIdx.x;  // 128 = NNE/4

    const float4 val = reinterpret_cast<const float4*>(g_y + b * NNE)[tid];

    const int t0 = blockIdx.x * ROWS_F;
    float4* o = reinterpret_cast<float4*>(out + ((size_t)b * NT + t0) * NNE);
    #pragma unroll 4
    for (int r = 0; r < ROWS_F; ++r)
        o[(size_t)r * (NNE / 4) + tid] = val;
}

// ============================================================
extern "C" void kernel_launch(void* const* d_in, const int* in_sizes, int n_in,
                              void* d_out, int out_size) {
    const float* x       = (const float*)d_in[0];
    const float* cat_emb = (const float*)d_in[1];
    const float* Wq      = (const float*)d_in[2];
    const float* Wk      = (const float*)d_in[3];
    const float* Wv      = (const float*)d_in[4];
    const float* Wp      = (const float*)d_in[5];
    const float* gamma   = (const float*)d_in[6];
    const float* beta    = (const float*)d_in[7];
    float* out = (float*)d_out;

    kA<<<NB, NNE>>>(cat_emb, Wq, Wk);
    kFuse<<<dim3(NBLK, NB), 256>>>(x);
    kE<<<NB, NNE>>>(Wv, Wp, gamma, beta);
    kF<<<dim3(NT / ROWS_F, NB), 128>>>(out);
}

// round 3
// speedup vs baseline: 1.2594x; 1.0063x over previous
#include <cuda_runtime.h>
#include <math.h>

#define NB   32      // batch
#define NT   4096    // sequence
#define NCAT 128
#define NNE  512
#define NHS  64

#define NBLK 32              // blocks per batch in fused kernel
#define TPB  (NT / NBLK)     // 128 t per block
#define WARPS 8
#define TPW  (TPB / WARPS)   // 16 rows per warp

// ---- scratch (device globals; no allocations allowed) ----
__device__ float g_qk[NB * NNE];              // folded scale * Wk @ (cat_emb @ Wq)
__device__ float g_pm[NB * NBLK];             // partial softmax offset (per block)
__device__ float g_ps[NB * NBLK];             // partial exp-sum (w.r.t. offset)
__device__ float g_pacc[NB * NBLK * NNE];     // partial weighted sums (unnormalized)
__device__ float g_y[NB * NNE];               // final per-batch row

// ============================================================
// Kernel A: q[b] = cat_emb[b] @ Wq ; qk[b,n] = scale * sum_h Wk[n,h] q[h]
// ============================================================
__global__ void kA(const float* __restrict__ cat_emb,
                   const float* __restrict__ Wq,
                   const float* __restrict__ Wk) {
    const int b = blockIdx.x;
    const int tid = threadIdx.x;
    __shared__ float qs[NHS];

    if (tid < NHS) {
        float acc = 0.f;
        const float* ce = cat_emb + b * NCAT;
        #pragma unroll 8
        for (int c = 0; c < NCAT; ++c)
            acc += ce[c] * Wq[c * NHS + tid];
        qs[tid] = acc;
    }
    __syncthreads();

    float acc = 0.f;
    const float* wkr = Wk + tid * NHS;
    #pragma unroll
    for (int h = 0; h < NHS; ++h)
        acc += wkr[h] * qs[h];
    g_qk[b * NNE + tid] = acc * 0.125f;  // 1/sqrt(64)
}

// ============================================================
// Fused kernel: scores + softmax-weighted x-sum in ONE pass over x.
// Fixed per-warp exp offset (= first row's score) instead of a running
// max: removes the serial rescale chain; mathematically identical softmax.
// grid: (NBLK, NB), 256 threads (8 warps). Warp owns TPW contiguous rows.
// ============================================================
__global__ void kFuse(const float* __restrict__ x) {
    const int b = blockIdx.y;
    const int blk = blockIdx.x;
    const int tid = threadIdx.x;
    const int warp = tid >> 5, lane = tid & 31;

    // qk in registers, same lane layout as x rows: float4 idx lane+32i
    const float4* qkp = reinterpret_cast<const float4*>(g_qk + b * NNE);
    float4 qv[4];
    #pragma unroll
    for (int i = 0; i < 4; ++i) qv[i] = qkp[lane + 32 * i];

    const int t0 = blk * TPB + warp * TPW;
    const float4* xbase = reinterpret_cast<const float4*>(
        x + ((size_t)b * NT + t0) * NNE);

    float4 acc[4];
    float d0, S;

    // ---- t = 0: establishes the exp offset; its weight is exp(0)=1 ----
    {
        float4 xv[4];
        #pragma unroll
        for (int i = 0; i < 4; ++i) xv[i] = xbase[lane + 32 * i];
        float d = 0.f;
        #pragma unroll
        for (int i = 0; i < 4; ++i)
            d += xv[i].x * qv[i].x + xv[i].y * qv[i].y +
                 xv[i].z * qv[i].z + xv[i].w * qv[i].w;
        #pragma unroll
        for (int o = 16; o > 0; o >>= 1)
            d += __shfl_xor_sync(0xffffffffu, d, o);
        d0 = d;
        S = 1.f;
        #pragma unroll
        for (int i = 0; i < 4; ++i) acc[i] = xv[i];
    }

    // ---- t = 1..TPW-1: independent per-row chains (no acc rescale) ----
    #pragma unroll 3
    for (int t = 1; t < TPW; ++t) {
        float4 xv[4];
        const float4* xr = xbase + (size_t)t * (NNE / 4);
        #pragma unroll
        for (int i = 0; i < 4; ++i) xv[i] = xr[lane + 32 * i];

        float d = 0.f;
        #pragma unroll
        for (int i = 0; i < 4; ++i)
            d += xv[i].x * qv[i].x + xv[i].y * qv[i].y +
                 xv[i].z * qv[i].z + xv[i].w * qv[i].w;
        #pragma unroll
        for (int o = 16; o > 0; o >>= 1)
            d += __shfl_xor_sync(0xffffffffu, d, o);

        const float w = __expf(d - d0);
        S += w;
        #pragma unroll
        for (int i = 0; i < 4; ++i) {
            acc[i].x = fmaf(w, xv[i].x, acc[i].x);
            acc[i].y = fmaf(w, xv[i].y, acc[i].y);
            acc[i].z = fmaf(w, xv[i].z, acc[i].z);
            acc[i].w = fmaf(w, xv[i].w, acc[i].w);
        }
    }

    // ---- block combine across 8 warps (offsets differ per warp) ----
    __shared__ float sm[WARPS], ss[WARPS];
    __shared__ float sacc[WARPS][NNE];  // 16 KB
    if (lane == 0) { sm[warp] = d0; ss[warp] = S; }
    float4* sa4 = reinterpret_cast<float4*>(sacc[warp]);
    #pragma unroll
    for (int i = 0; i < 4; ++i) sa4[lane + 32 * i] = acc[i];
    __syncthreads();

    float mb = sm[0];
    #pragma unroll
    for (int w2 = 1; w2 < WARPS; ++w2) mb = fmaxf(mb, sm[w2]);

    float a0 = 0.f, a1 = 0.f, Sb = 0.f;
    #pragma unroll
    for (int w2 = 0; w2 < WARPS; ++w2) {
        const float f = __expf(sm[w2] - mb);
        Sb += ss[w2] * f;
        a0 += sacc[w2][tid] * f;
        a1 += sacc[w2][tid + 256] * f;
    }
    const int p = b * NBLK + blk;
    g_pacc[(size_t)p * NNE + tid]       = a0;
    g_pacc[(size_t)p * NNE + tid + 256] = a1;
    if (tid == 0) { g_pm[p] = mb; g_ps[p] = Sb; }
}

// ============================================================
// Kernel E: combine partials -> xa; out = xa@Wv; y = out@Wp; LayerNorm -> g_y
// grid: NB blocks, 512 threads (16 warps)
// ============================================================
__global__ void kE(const float* __restrict__ Wv,
                   const float* __restrict__ Wp,
                   const float* __restrict__ gamma,
                   const float* __restrict__ beta) {
    const int b = blockIdx.x;
    const int tid = threadIdx.x;
    const int warp = tid >> 5, lane = tid & 31;

    __shared__ float xa[NNE];
    __shared__ float outh[NHS];
    __shared__ float red[16];
    __shared__ float bcast;

    float mb = -INFINITY;
    #pragma unroll
    for (int c = 0; c < NBLK; ++c)
        mb = fmaxf(mb, g_pm[b * NBLK + c]);
    float Sb = 0.f;
    #pragma unroll
    for (int c = 0; c < NBLK; ++c)
        Sb += g_ps[b * NBLK + c] * __expf(g_pm[b * NBLK + c] - mb);

    float acc = 0.f;
    #pragma unroll
    for (int c = 0; c < NBLK; ++c)
        acc += g_pacc[((size_t)b * NBLK + c) * NNE + tid] *
               __expf(g_pm[b * NBLK + c] - mb);
    xa[tid] = acc / Sb;
    __syncthreads();

    if (tid < NHS) {
        float o = 0.f;
        #pragma unroll 8
        for (int n = 0; n < NNE; ++n)
            o += xa[n] * Wv[n * NHS + tid];
        outh[tid] = o;
    }
    __syncthreads();

    float y = 0.f;
    #pragma unroll
    for (int h = 0; h < NHS; ++h)
        y += outh[h] * Wp[h * NNE + tid];

    // mean
    float s = y;
    #pragma unroll
    for (int o = 16; o > 0; o >>= 1)
        s += __shfl_xor_sync(0xffffffffu, s, o);
    if (lane == 0) red[warp] = s;
    __syncthreads();
    if (tid < 32) {
        float ss2 = (tid < 16) ? red[tid] : 0.f;
        #pragma unroll
        for (int o = 16; o > 0; o >>= 1)
            ss2 += __shfl_xor_sync(0xffffffffu, ss2, o);
        if (tid == 0) bcast = ss2;
    }
    __syncthreads();
    const float mu = bcast * (1.f / NNE);
    __syncthreads();

    // variance
    const float d = y - mu;
    float vs = d * d;
    #pragma unroll
    for (int o = 16; o > 0; o >>= 1)
        vs += __shfl_xor_sync(0xffffffffu, vs, o);
    if (lane == 0) red[warp] = vs;
    __syncthreads();
    if (tid < 32) {
        float ss2 = (tid < 16) ? red[tid] : 0.f;
        #pragma unroll
        for (int o = 16; o > 0; o >>= 1)
            ss2 += __shfl_xor_sync(0xffffffffu, ss2, o);
        if (tid == 0) bcast = ss2;
    }
    __syncthreads();
    const float var = bcast * (1.f / NNE);
    const float rstd = rsqrtf(var + 1e-5f);

    g_y[b * NNE + tid] = d * rstd * gamma[tid] + beta[tid];
}

// ============================================================
// Kernel F: broadcast g_y[b,:] to out[b, t, :] for all t.
// 256 threads, 64 rows/block, streaming stores (bypass L2 retention).
// ============================================================
#define ROWS_F 64
__global__ void kF(float* __restrict__ out) {
    const int b = blockIdx.y;
    const int tid = threadIdx.x;          // 256
    const int col = tid & 127;            // float4 column within row
    const int half = tid >> 7;            // 0/1: which of 2 rows per iter

    const float4 val = reinterpret_cast<const float4*>(g_y + b * NNE)[col];

    const int t0 = blockIdx.x * ROWS_F;
    float4* o = reinterpret_cast<float4*>(out + ((size_t)b * NT + t0) * NNE);
    #pragma unroll 8
    for (int r = 0; r < ROWS_F / 2; ++r)
        __stcs(&o[(size_t)(r * 2 + half) * (NNE / 4) + col], val);
}

// ============================================================
extern "C" void kernel_launch(void* const* d_in, const int* in_sizes, int n_in,
                              void* d_out, int out_size) {
    const float* x       = (const float*)d_in[0];
    const float* cat_emb = (const float*)d_in[1];
    const float* Wq      = (const float*)d_in[2];
    const float* Wk      = (const float*)d_in[3];
    const float* Wv      = (const float*)d_in[4];
    const float* Wp      = (const float*)d_in[5];
    const float* gamma   = (const float*)d_in[6];
    const float* beta    = (const float*)d_in[7];
    float* out = (float*)d_out;

    kA<<<NB, NNE>>>(cat_emb, Wq, Wk);
    kFuse<<<dim3(NBLK, NB), 256>>>(x);
    kE<<<NB, NNE>>>(Wv, Wp, gamma, beta);
    kF<<<dim3(NT / ROWS_F, NB), 256>>>(out);
}